// round 7
// baseline (speedup 1.0000x reference)
#include <cuda_runtime.h>
#include <math.h>

// Problem constants (fixed by the dataset)
#define BATCH   512
#define IN_DIM  128
#define OUT_DIM 128
#define NFEAT   9                  // silu + 8 basis functions
#define IPB     8                  // input dims per block (k-split granularity)
#define KC      (IPB * NFEAT)      // 72 k per block
#define SPLITS  (IN_DIM / IPB)     // 16 k-splits
#define BM      64                 // batch rows per block
#define MT      (BATCH / BM)       // 8 m-tiles
#define NBLK    (MT * SPLITS)      // 128 blocks (single wave on 148 SMs)
#define NTHR    512
#define FS2_STR 66                 // Fs2 row stride in 8-byte entries (even!)
#define WS_STR  132                // Ws row stride in floats (16B multiple)
#define NOUT    (BATCH * OUT_DIM)  // 65536

// Scratch (device globals — no allocation in kernel_launch)
__device__ float        g_P[SPLITS * NOUT];  // split-K partials (4.2 MB)
__device__ unsigned int g_bar;               // monotonic barrier ticket counter

// ---------------------------------------------------------------------------
// f32x2 packed helpers (sm_103a FFMA2 — ptxas never emits this from C++)
// ---------------------------------------------------------------------------
__device__ __forceinline__ unsigned long long dup_f32x2(float v) {
    unsigned long long d;
    unsigned int u = __float_as_uint(v);
    asm("mov.b64 %0, {%1, %1};" : "=l"(d) : "r"(u));
    return d;
}
__device__ __forceinline__ void ffma2(unsigned long long& acc,
                                      unsigned long long a,
                                      unsigned long long b) {
    asm("fma.rn.f32x2 %0, %1, %2, %0;" : "+l"(acc) : "l"(a), "l"(b));
}

// ---------------------------------------------------------------------------
// Single persistent kernel, 512 threads, 128 blocks (single wave):
//   phase 1: build Fs2 (pre-duplicated f32x2 features) + Ws in smem,
//            f32x2 GEMM with 2-D warp tiling -> partials
//   grid barrier (monotonic ticket; replay-safe)
//   phase 2: 65536 threads reduce the L2-warm partials -> out
// ---------------------------------------------------------------------------
__global__ void __launch_bounds__(NTHR, 1)
fused_kernel(const float* __restrict__ x,
             const float* __restrict__ grid,
             const float* __restrict__ coef,
             const float* __restrict__ sb,
             const float* __restrict__ ss,
             const float* __restrict__ mask,
             float* __restrict__ out) {
    __shared__ unsigned long long Fs2[KC * FS2_STR]; // 37.1 KB, [k][m] dup'd
    __shared__ float              Ws [KC * WS_STR];  // 38.0 KB, [k][o]

    const int t  = threadIdx.x;
    const int m0 = blockIdx.x * BM;
    const int i0 = blockIdx.y * IPB;

    // ---- uniform extended knot vector (division-free) ----
    const float g0 = grid[0];
    const float g5 = grid[5];
    const float step = (g5 - g0) * 0.2f;
    const float inv1 = __frcp_rn(step);
    const float invr[3] = { inv1, 0.5f * inv1, inv1 * (1.0f / 3.0f) };

    float tk[12];
    tk[0]  = g0 - step * 3.0f;
    tk[1]  = g0 - step * 2.0f;
    tk[2]  = g0 - step;
    tk[3]  = g0;
    tk[4]  = grid[1];
    tk[5]  = grid[2];
    tk[6]  = grid[3];
    tk[7]  = grid[4];
    tk[8]  = g5;
    tk[9]  = g5 + step;
    tk[10] = g5 + step * 2.0f;
    tk[11] = g5 + step * 3.0f;

    // ---- Fs2 build: 64 n x 8 i = 512 x-values, 1 per thread ----
    {
        const int il = t & 7;
        const int nl = t >> 3;
        const float xv = __ldg(&x[(m0 + nl) * IN_DIM + i0 + il]);

        const float sig  = __frcp_rn(1.0f + __expf(-xv));
        const float silu = xv * sig;

        float B[11];
#pragma unroll
        for (int m = 0; m < 11; m++)
            B[m] = (xv >= tk[m] && xv < tk[m + 1]) ? 1.0f : 0.0f;
#pragma unroll
        for (int r = 1; r <= 3; r++) {
            const float iv = invr[r - 1];
#pragma unroll
            for (int m = 0; m < 11 - r; m++) {
                float alpha = (xv - tk[m]) * iv;
                float beta  = (tk[m + r + 1] - xv) * iv;
                B[m] = alpha * B[m] + beta * B[m + 1];
            }
        }

        const int kb = il * NFEAT;
        Fs2[kb * FS2_STR + nl] = dup_f32x2(silu);
#pragma unroll
        for (int j = 0; j < 8; j++)
            Fs2[(kb + 1 + j) * FS2_STR + nl] = dup_f32x2(B[j]);
    }

    // ---- Ws build: 128 o x 8 i = 1024 (o,i) pairs, 2 per thread ----
#pragma unroll
    for (int q = 0; q < 2; q++) {
        const int p = t + NTHR * q;
        const int o = p >> 3;
        const int i = p & 7;
        const int s = o * IN_DIM + i0 + i;

        const float4 c0 = __ldg((const float4*)&coef[s * 8]);
        const float4 c1 = __ldg((const float4*)&coef[s * 8 + 4]);
        const float mk  = __ldg(&mask[s]);
        const float wb  = mk * __ldg(&sb[s]);
        const float ws  = mk * __ldg(&ss[s]);

        const int kb = i * NFEAT;
        Ws[kb * WS_STR + o]       = wb;
        Ws[(kb + 1) * WS_STR + o] = ws * c0.x;
        Ws[(kb + 2) * WS_STR + o] = ws * c0.y;
        Ws[(kb + 3) * WS_STR + o] = ws * c0.z;
        Ws[(kb + 4) * WS_STR + o] = ws * c0.w;
        Ws[(kb + 5) * WS_STR + o] = ws * c1.x;
        Ws[(kb + 6) * WS_STR + o] = ws * c1.y;
        Ws[(kb + 7) * WS_STR + o] = ws * c1.z;
        Ws[(kb + 8) * WS_STR + o] = ws * c1.w;
    }

    __syncthreads();

    // ---- GEMM: 2-D warp tiling, 4m x 4o per thread, packed f32x2 ----
    // warp = (wm, wo) in 4 x 4; lane = (lm, lo) in 4 x 8.
    const int lane = t & 31;
    const int warp = t >> 5;
    const int mOff = (warp & 3) * 16 + (lane >> 3) * 4;  // m index (8B entries)
    const int oOff = (warp >> 2) * 32 + (lane & 7) * 4;  // o float index

    unsigned long long acc[4][2];       // 4 m-rows x 2 o-pairs
#pragma unroll
    for (int a = 0; a < 4; a++) { acc[a][0] = 0ULL; acc[a][1] = 0ULL; }

#pragma unroll 6
    for (int k = 0; k < KC; k++) {
        const unsigned long long* fp = &Fs2[k * FS2_STR + mOff];
        const ulonglong2 fA = *(const ulonglong2*)fp;        // fd0, fd1
        const ulonglong2 fB = *(const ulonglong2*)(fp + 2);  // fd2, fd3
        const ulonglong2 w  = *(const ulonglong2*)&Ws[k * WS_STR + oOff];

        ffma2(acc[0][0], fA.x, w.x); ffma2(acc[0][1], fA.x, w.y);
        ffma2(acc[1][0], fA.y, w.x); ffma2(acc[1][1], fA.y, w.y);
        ffma2(acc[2][0], fB.x, w.x); ffma2(acc[2][1], fB.x, w.y);
        ffma2(acc[3][0], fB.y, w.x); ffma2(acc[3][1], fB.y, w.y);
    }

    float* P = &g_P[blockIdx.y * NOUT];
#pragma unroll
    for (int a = 0; a < 4; a++) {
        const int row = m0 + mOff + a;
        ulonglong2 v; v.x = acc[a][0]; v.y = acc[a][1];
        *(ulonglong2*)&P[row * OUT_DIM + oOff] = v;
    }

    // ---- grid barrier (monotonic ticket; works across graph replays) ----
    __threadfence();
    __syncthreads();
    __shared__ unsigned int s_target;
    if (t == 0) {
        unsigned int ticket = atomicAdd(&g_bar, 1u);
        s_target = ticket - (ticket & (NBLK - 1)) + NBLK;  // epoch base + 128
    }
    __syncthreads();
    if (t == 0) {
        const unsigned int target = s_target;
        while (*(volatile unsigned int*)&g_bar < target) { }
    }
    __syncthreads();
    __threadfence();

    // ---- phase 2: reduce L2-warm partials, 1 output per thread ----
    const int flat = blockIdx.y * MT + blockIdx.x;   // 0..127
    const int idx  = flat * NTHR + t;                // 0..65535
    float v[SPLITS];
#pragma unroll
    for (int q = 0; q < SPLITS; q++)
        v[q] = g_P[q * NOUT + idx];
    float s = 0.0f;
#pragma unroll
    for (int q = 0; q < SPLITS; q++)
        s += v[q];
    out[idx] = s;
}

// ---------------------------------------------------------------------------
extern "C" void kernel_launch(void* const* d_in, const int* in_sizes, int n_in,
                              void* d_out, int out_size) {
    const float* x    = (const float*)d_in[0];
    const float* grid = (const float*)d_in[1];
    const float* coef = (const float*)d_in[2];
    const float* sb   = (const float*)d_in[3];
    const float* ss   = (const float*)d_in[4];
    const float* mask = (const float*)d_in[5];
    float* out = (float*)d_out;

    fused_kernel<<<dim3(MT, SPLITS), NTHR>>>(x, grid, coef, sb, ss, mask, out);
}